// round 6
// baseline (speedup 1.0000x reference)
#include <cuda_runtime.h>

// HMM forward: alpha_{t+1} = (alpha_t @ A) * Bo[t],  answer = sum(alpha_{T-1})
//
// R6: 148 persistent CTAs (was 128) to enlist idle SMs' RF+SMEM as pin space.
// 136 CTAs own 7 float4 column-groups, 12 own 6 (1024 groups total).
// 224 threads = 7 warps; warp w handles group start+w; lane = row slot.
// Per-column math identical to R1..R5 (i = lane+32k, k ascending; xor
// butterfly == R1's tree) -> per-step alpha bit-identical.
//
// Tiers per column strip:  rows [0,1408) registers (44 x ulonglong2),
//   rows [1408,3328) SMEM (60 k-slots, 231.5KB), rows [3328,4096) L2 via
//   transposed copy g_A3T (768 rows; 12.7MB/step chip-wide, was 16.5MB).

#define N_STATES 4096
#define SEQ_T    1024
#define N_OBS    128
#define NCTA     148
#define NTHR     224
#define NW       7
#define BIGCTAS  136                 // CTAs owning 7 groups (rest own 6)

#define KR 44
#define KS 60
#define KT 24                        // 44+60+24 = 128
#define R_ROWS (KR * 32)             // 1408
#define S_ROWS (KS * 32)             // 1920
#define T3_OFF (R_ROWS + S_ROWS)     // 3328
#define T3_ROWS (KT * 32)            // 768
#define S_PITCH (S_ROWS + 1)         // 1921

// dynamic smem: sA[NW][S_PITCH] float4 + s_alpha[4096] float = 231,536 B
#define SMEM_BYTES (NW * S_PITCH * 16 + N_STATES * 4)

__device__ float    g_Bo[SEQ_T * N_STATES];
__device__ float4   g_A3T[1024 * T3_ROWS];     // [col_group][row - T3_OFF]
__device__ float    g_alpha[2][N_STATES];
__device__ unsigned g_count;
__device__ unsigned g_sense;   // even #barriers per launch -> restored

// ---------------------------------------------------------------------------
__global__ void gather_Bo_kernel(const float* __restrict__ B,
                                 const int*   __restrict__ obs_raw) {
    int any = 0;
    for (int k = 1 + 2 * (int)threadIdx.x; k < 1024; k += 2 * (int)blockDim.x)
        any |= obs_raw[k];
    int is32 = __syncthreads_or(any);

    int t = blockIdx.x;
    int o = is32 ? obs_raw[t] : obs_raw[2 * t];

    for (int j = threadIdx.x; j < N_STATES; j += blockDim.x)
        g_Bo[t * N_STATES + j] = B[j * N_OBS + o];
}

// ---------------------------------------------------------------------------
// Tiled transpose of rows [T3_OFF, 4096) of A into g_A3T.
__global__ void transpose_A3_kernel(const float* __restrict__ A) {
    __shared__ float4 tile[32][33];
    const float4* A4 = reinterpret_cast<const float4*>(A);
    int r0 = blockIdx.x * 32;            // 24 tiles over 768 rows
    int c0 = blockIdx.y * 32;            // 32 tiles over 1024 col-groups
    int tx = threadIdx.x & 31, ty = threadIdx.x >> 5;
    #pragma unroll
    for (int p = 0; p < 4; ++p) {
        int r = r0 + ty + 8 * p;
        tile[ty + 8 * p][tx] = A4[(size_t)(T3_OFF + r) * 1024 + (c0 + tx)];
    }
    __syncthreads();
    #pragma unroll
    for (int p = 0; p < 4; ++p) {
        int c = c0 + ty + 8 * p;
        g_A3T[(size_t)c * T3_ROWS + (r0 + tx)] = tile[tx][ty + 8 * p];
    }
}

// ---------------------------------------------------------------------------
__device__ __forceinline__ void grid_barrier(unsigned& local_sense, unsigned nblocks) {
    __syncthreads();
    if (threadIdx.x == 0) {
        unsigned s = local_sense ^ 1u;
        local_sense = s;
        __threadfence();
        if (atomicAdd(&g_count, 1u) == nblocks - 1u) {
            g_count = 0u;
            __threadfence();
            atomicExch(&g_sense, s);
        } else {
            while (*(volatile unsigned*)&g_sense != s) { }
        }
        __threadfence();
    }
    __syncthreads();
}

// packed f32x2 fma: component-wise IEEE fp32 fma (bit-identical to scalar)
__device__ __forceinline__ void fma2(unsigned long long& d,
                                     unsigned long long v,
                                     unsigned long long a) {
    asm("fma.rn.f32x2 %0, %1, %2, %0;" : "+l"(d) : "l"(v), "l"(a));
}
__device__ __forceinline__ unsigned long long pack2(float a) {
    unsigned long long r;
    asm("mov.b64 %0, {%1, %2};" : "=l"(r) : "f"(a), "f"(a));
    return r;
}

// ---------------------------------------------------------------------------
__global__ void __launch_bounds__(NTHR, 1)
hmm_forward_kernel(const float* __restrict__ A,
                   const float* __restrict__ pi,
                   float*       __restrict__ out) {
    extern __shared__ float smem[];
    float4* sA      = reinterpret_cast<float4*>(smem);        // [NW][S_PITCH]
    float*  s_alpha = smem + NW * S_PITCH * 4;                // 4096 floats

    const int tid  = threadIdx.x;
    const int cta  = blockIdx.x;
    const int lane = tid & 31;            // row slot rs
    const int cg   = tid >> 5;            // warp id = local column group, 0..6

    // column-group ownership: first BIGCTAS CTAs own 7 groups, rest own 6
    const int cnt   = (cta < BIGCTAS) ? 7 : 6;
    const int start = (cta < BIGCTAS) ? 7 * cta
                                      : 7 * BIGCTAS + 6 * (cta - BIGCTAS);
    const bool active = (cg < cnt);
    const int gcg  = start + cg;          // global float4 column group
    const int col0 = start * 4;

    const ulonglong2* __restrict__ A4u =
        reinterpret_cast<const ulonglong2*>(A);
    const float4* __restrict__ A4base =
        reinterpret_cast<const float4*>(A) + start;

    // ---- prologue: tier-1 rows in registers ----
    ulonglong2 rA[KR];
    if (active) {
        #pragma unroll
        for (int k = 0; k < KR; ++k)
            rA[k] = A4u[(size_t)(lane + 32 * k) * 1024 + gcg];
    }

    // ---- prologue: tier-2 rows into SMEM, [group][row] layout ----
    for (int idx = tid; idx < S_ROWS * NW; idx += NTHR) {
        int w  = idx % NW;
        int rr = idx / NW;
        if (w < cnt)
            sA[w * S_PITCH + rr] = A4base[(size_t)(R_ROWS + rr) * 1024 + w];
    }

    const ulonglong2* __restrict__ sAw =
        reinterpret_cast<const ulonglong2*>(sA + cg * S_PITCH);
    const ulonglong2* __restrict__ A3w =
        reinterpret_cast<const ulonglong2*>(g_A3T) + (size_t)gcg * T3_ROWS;

    unsigned local_sense = 0;

    // ---- alpha0 = pi * Bo[0] (this CTA's cnt*4 columns) ----
    if (tid < cnt * 4) {
        int j = col0 + tid;
        g_alpha[0][j] = pi[j] * g_Bo[j];
    }
    grid_barrier(local_sense, gridDim.x);          // barrier #1

    int cur = 0;
    for (int t = 1; t < SEQ_T; ++t) {
        // prefetch emission row early (independent of alpha)
        float4 bo;
        if (lane == 0 && active)
            bo = reinterpret_cast<const float4*>(g_Bo + t * N_STATES)[gcg];

        // stage alpha into smem (1024 float4)
        {
            const float4* asrc = reinterpret_cast<const float4*>(g_alpha[cur]);
            float4*       adst = reinterpret_cast<float4*>(s_alpha);
            #pragma unroll
            for (int i = tid; i < 1024; i += NTHR)
                adst[i] = asrc[i];
        }
        __syncthreads();

        if (active) {
            // dot partials: i = lane + 32k, k ascending 0..127 (order contract)
            unsigned long long acc01 = 0ull, acc23 = 0ull;

            #pragma unroll
            for (int k = 0; k < KR; ++k) {               // tier 1: registers
                unsigned long long aa = pack2(s_alpha[lane + 32 * k]);
                fma2(acc01, rA[k].x, aa);
                fma2(acc23, rA[k].y, aa);
            }
            #pragma unroll 10
            for (int k = 0; k < KS; ++k) {               // tier 2: SMEM
                unsigned long long aa = pack2(s_alpha[R_ROWS + lane + 32 * k]);
                ulonglong2 v = sAw[lane + 32 * k];
                fma2(acc01, v.x, aa);
                fma2(acc23, v.y, aa);
            }
            #pragma unroll 8
            for (int k = 0; k < KT; ++k) {               // tier 3: L2 (transposed)
                unsigned long long aa = pack2(s_alpha[T3_OFF + lane + 32 * k]);
                ulonglong2 v = A3w[lane + 32 * k];
                fma2(acc01, v.x, aa);
                fma2(acc23, v.y, aa);
            }

            // unpack + xor butterfly (== R1's 32-slot tree at lane 0)
            float4 r;
            asm("mov.b64 {%0, %1}, %2;" : "=f"(r.x), "=f"(r.y) : "l"(acc01));
            asm("mov.b64 {%0, %1}, %2;" : "=f"(r.z), "=f"(r.w) : "l"(acc23));
            #pragma unroll
            for (int m = 16; m > 0; m >>= 1) {
                r.x += __shfl_xor_sync(0xffffffffu, r.x, m);
                r.y += __shfl_xor_sync(0xffffffffu, r.y, m);
                r.z += __shfl_xor_sync(0xffffffffu, r.z, m);
                r.w += __shfl_xor_sync(0xffffffffu, r.w, m);
            }

            if (lane == 0) {
                float4 o4;
                o4.x = r.x * bo.x; o4.y = r.y * bo.y;
                o4.z = r.z * bo.z; o4.w = r.w * bo.w;
                reinterpret_cast<float4*>(g_alpha[cur ^ 1])[gcg] = o4;
            }
        }

        grid_barrier(local_sense, gridDim.x);      // barriers #2..#1024 (even)
        cur ^= 1;
    }

    // ---- final sum (CTA 0, 224 threads) ----
    if (cta == 0) {
        float s = 0.f;
        for (int i = tid; i < N_STATES; i += NTHR)
            s += g_alpha[cur][i];
        s_alpha[tid] = s;
        __syncthreads();
        if (tid < 112) s_alpha[tid] += s_alpha[tid + 112]; __syncthreads();
        if (tid < 56)  s_alpha[tid] += s_alpha[tid + 56];  __syncthreads();
        if (tid < 28)  s_alpha[tid] += s_alpha[tid + 28];  __syncthreads();
        if (tid < 14)  s_alpha[tid] += s_alpha[tid + 14];  __syncthreads();
        if (tid < 7)   s_alpha[tid] += s_alpha[tid + 7];   __syncthreads();
        if (tid == 0) {
            float r = s_alpha[0];
            #pragma unroll
            for (int i = 1; i < 7; ++i) r += s_alpha[i];
            out[0] = r;
        }
    }
}

// ---------------------------------------------------------------------------
extern "C" void kernel_launch(void* const* d_in, const int* in_sizes, int n_in,
                              void* d_out, int out_size) {
    const float* A   = (const float*)d_in[0];
    const float* B   = (const float*)d_in[1];
    const float* pi  = (const float*)d_in[2];
    const int*   obs = (const int*)d_in[3];
    float* out = (float*)d_out;

    cudaFuncSetAttribute(hmm_forward_kernel,
                         cudaFuncAttributeMaxDynamicSharedMemorySize, SMEM_BYTES);

    gather_Bo_kernel<<<SEQ_T, 256>>>(B, obs);
    dim3 tgrid(T3_ROWS / 32, 1024 / 32);
    transpose_A3_kernel<<<tgrid, 256>>>(A);
    hmm_forward_kernel<<<NCTA, NTHR, SMEM_BYTES>>>(A, pi, out);
}